// round 14
// baseline (speedup 1.0000x reference)
#include <cuda_runtime.h>
#include <math_constants.h>

// x: (64, 4096, 256) fp32; top-8 over axis 1 (S), sorted desc -> (64, 8, 256)
#define B_DIM 64
#define S_DIM 4096
#define C_DIM 256
#define K_TOP 8

#define CHUNKS 16
#define CHUNK_S (S_DIM / CHUNKS)        // 256
#define PAIRS_PER_BLOCK 2               // 256 threads = 2 (b,chunk) pairs x 128 lanes
#define GRID1 (B_DIM * CHUNKS / PAIRS_PER_BLOCK)  // 512 blocks
#define BLOCKS_PER_BATCH (CHUNKS / PAIRS_PER_BLOCK)  // 8

// Partials, layout [b][c][chunk][k]: 8 MiB static scratch.
// For fixed (b,c) the CHUNKS*K_TOP=128 candidates are 512B contiguous.
__device__ __align__(256) float g_partial[B_DIM * C_DIM * CHUNKS * K_TOP];
// Per-batch completion counters (zero at load; last block resets -> replay-safe).
__device__ int g_cnt[B_DIM];

// Compare-exchange keeping max at 'a' (descending order).
__device__ __forceinline__ void ce(float& a, float& b) {
    float hi = fmaxf(a, b);
    float lo = fminf(a, b);
    a = hi; b = lo;
}

// Batcher odd-even mergesort, n=8, 19 CE, descending.
__device__ __forceinline__ void sort8_desc(float (&f)[8]) {
    ce(f[0],f[1]); ce(f[2],f[3]); ce(f[4],f[5]); ce(f[6],f[7]);
    ce(f[0],f[2]); ce(f[1],f[3]); ce(f[4],f[6]); ce(f[5],f[7]);
    ce(f[1],f[2]); ce(f[5],f[6]);
    ce(f[0],f[4]); ce(f[1],f[5]); ce(f[2],f[6]); ce(f[3],f[7]);
    ce(f[2],f[4]); ce(f[3],f[5]);
    ce(f[1],f[2]); ce(f[3],f[4]); ce(f[5],f[6]);
}

// Exact sorted top-8 of the union of two descending-sorted 8-lists.
__device__ __forceinline__ void merge8_desc(float (&t)[8], const float (&g)[8]) {
    #pragma unroll
    for (int i = 0; i < 8; ++i) t[i] = fmaxf(t[i], g[7 - i]);
    ce(t[0],t[4]); ce(t[1],t[5]); ce(t[2],t[6]); ce(t[3],t[7]);
    ce(t[0],t[2]); ce(t[1],t[3]); ce(t[4],t[6]); ce(t[5],t[7]);
    ce(t[0],t[1]); ce(t[2],t[3]); ce(t[4],t[5]); ce(t[6],t[7]);
}

// Fused: R8's streaming pass (verbatim) + fence-free last-block-per-batch merge.
__global__ __launch_bounds__(256, 3) void kmax_fused_kernel(
    const float2* __restrict__ x2, float* __restrict__ out)
{
    const int sub  = threadIdx.x >> 7;          // 0..1
    const int lane = threadIdx.x & 127;         // float2 channel group
    const int pair = blockIdx.x * PAIRS_PER_BLOCK + sub;
    const int batch = pair >> 4;                // / CHUNKS (uniform per block)
    const int chunk = pair & (CHUNKS - 1);

    const float2* __restrict__ p =
        x2 + ((size_t)batch * S_DIM + (size_t)chunk * CHUNK_S) * (C_DIM / 2) + lane;

    float t0[8], t1[8];
    #pragma unroll
    for (int i = 0; i < 8; ++i) { t0[i] = -CUDART_INF_F; t1[i] = -CUDART_INF_F; }

    #pragma unroll 1
    for (int s = 0; s < CHUNK_S; s += 16) {
        float2 buf[16];
        #pragma unroll
        for (int u = 0; u < 16; ++u)
            buf[u] = __ldcs(p + (size_t)(s + u) * (C_DIM / 2));

        float f[8], g[8];
        // channel .x
        #pragma unroll
        for (int u = 0; u < 8; ++u) { f[u] = buf[u].x; g[u] = buf[u + 8].x; }
        sort8_desc(f); sort8_desc(g);
        merge8_desc(f, g);      // f = sorted top-8 of the 16
        merge8_desc(t0, f);
        // channel .y
        #pragma unroll
        for (int u = 0; u < 8; ++u) { f[u] = buf[u].y; g[u] = buf[u + 8].y; }
        sort8_desc(f); sort8_desc(g);
        merge8_desc(f, g);
        merge8_desc(t1, f);
    }

    // Store partials: [b][c][chunk][k]; 64B contiguous per thread (4x STG.128).
    {
        const int c0 = lane * 2;
        float4* __restrict__ o0 = (float4*)(g_partial
            + (((size_t)batch * C_DIM + c0) * CHUNKS + chunk) * K_TOP);
        float4* __restrict__ o1 = (float4*)(g_partial
            + (((size_t)batch * C_DIM + c0 + 1) * CHUNKS + chunk) * K_TOP);
        o0[0] = make_float4(t0[0], t0[1], t0[2], t0[3]);
        o0[1] = make_float4(t0[4], t0[5], t0[6], t0[7]);
        o1[0] = make_float4(t1[0], t1[1], t1[2], t1[3]);
        o1[1] = make_float4(t1[4], t1[5], t1[6], t1[7]);
    }

    // Fence-free completion: __syncthreads gives intra-block happens-before;
    // ONE acq_rel atomic per block publishes the block's stores (release) and,
    // for the last arriver, orders the merge reads (acquire). No membar flood.
    __shared__ int s_last;
    __syncthreads();
    if (threadIdx.x == 0) {
        int old;
        asm volatile("atom.add.acq_rel.gpu.global.s32 %0, [%1], 1;"
                     : "=r"(old) : "l"(&g_cnt[batch]) : "memory");
        s_last = (old == BLOCKS_PER_BATCH - 1) ? 1 : 0;
    }
    __syncthreads();
    if (!s_last) return;

    // Last block of this batch: reset counter for next replay, then merge.
    if (threadIdx.x == 0) g_cnt[batch] = 0;

    const int c = threadIdx.x;                  // one channel per thread
    const float4* __restrict__ pp = (const float4*)(g_partial
        + ((size_t)batch * C_DIM + c) * (CHUNKS * K_TOP));  // 512B contiguous

    float m[8];
    {
        float4 a = __ldcg(pp + 0);
        float4 d = __ldcg(pp + 1);
        m[0] = a.x; m[1] = a.y; m[2] = a.z; m[3] = a.w;
        m[4] = d.x; m[5] = d.y; m[6] = d.z; m[7] = d.w;
    }
    #pragma unroll 1
    for (int j = 1; j < CHUNKS; j += 3) {       // batch 3 records = 6 LDG.128
        float4 r[6];
        #pragma unroll
        for (int u = 0; u < 6; ++u)
            r[u] = __ldcg(pp + 2 * j + u);
        #pragma unroll
        for (int rec = 0; rec < 3; ++rec) {
            float g[8];
            g[0] = r[2*rec].x;   g[1] = r[2*rec].y;
            g[2] = r[2*rec].z;   g[3] = r[2*rec].w;
            g[4] = r[2*rec+1].x; g[5] = r[2*rec+1].y;
            g[6] = r[2*rec+1].z; g[7] = r[2*rec+1].w;
            merge8_desc(m, g);
        }
    }

    float* __restrict__ o = out + (size_t)batch * K_TOP * C_DIM + c;
    #pragma unroll
    for (int k = 0; k < K_TOP; ++k)
        o[(size_t)k * C_DIM] = m[k];
}

extern "C" void kernel_launch(void* const* d_in, const int* in_sizes, int n_in,
                              void* d_out, int out_size) {
    const float2* x2 = (const float2*)d_in[0];
    float* out = (float*)d_out;
    kmax_fused_kernel<<<GRID1, 256>>>(x2, out);
}

// round 15
// speedup vs baseline: 1.2438x; 1.2438x over previous
#include <cuda_runtime.h>
#include <math_constants.h>

// x: (64, 4096, 256) fp32; top-8 over axis 1 (S), sorted desc -> (64, 8, 256)
#define B_DIM 64
#define S_DIM 4096
#define C_DIM 256
#define K_TOP 8

#define QDIV 16                         // S-segments per channel (one per thread row)
#define SEG (S_DIM / QDIV)              // 256 s-values per thread (same as proven CHUNK_S)
#define CPB 16                          // channel-pairs per block (32 channels)
#define NCG (C_DIM / 2 / CPB)           // 8 channel groups
#define GRID1 (B_DIM * NCG)             // 512 blocks x 256 threads

// Compare-exchange keeping max at 'a' (descending order).
__device__ __forceinline__ void ce(float& a, float& b) {
    float hi = fmaxf(a, b);
    float lo = fminf(a, b);
    a = hi; b = lo;
}

// Batcher odd-even mergesort, n=8, 19 CE, descending.
__device__ __forceinline__ void sort8_desc(float (&f)[8]) {
    ce(f[0],f[1]); ce(f[2],f[3]); ce(f[4],f[5]); ce(f[6],f[7]);
    ce(f[0],f[2]); ce(f[1],f[3]); ce(f[4],f[6]); ce(f[5],f[7]);
    ce(f[1],f[2]); ce(f[5],f[6]);
    ce(f[0],f[4]); ce(f[1],f[5]); ce(f[2],f[6]); ce(f[3],f[7]);
    ce(f[2],f[4]); ce(f[3],f[5]);
    ce(f[1],f[2]); ce(f[3],f[4]); ce(f[5],f[6]);
}

// Exact sorted top-8 of the union of two descending-sorted 8-lists.
__device__ __forceinline__ void merge8_desc(float (&t)[8], const float (&g)[8]) {
    #pragma unroll
    for (int i = 0; i < 8; ++i) t[i] = fmaxf(t[i], g[7 - i]);
    ce(t[0],t[4]); ce(t[1],t[5]); ce(t[2],t[6]); ce(t[3],t[7]);
    ce(t[0],t[2]); ce(t[1],t[3]); ce(t[4],t[6]); ce(t[5],t[7]);
    ce(t[0],t[1]); ce(t[2],t[3]); ce(t[4],t[5]); ce(t[6],t[7]);
}

// Single-pass kernel: block = (batch, channel-group of 32 channels).
// Thread (q, cp) streams S-segment q of channel-pair cp with the proven
// R8 inner loop, then the block merges its 16 segments through shared
// memory. No global scratch, no second kernel, no inter-block protocol.
__global__ __launch_bounds__(256, 3) void kmax_onepass_kernel(
    const float2* __restrict__ x2, float* __restrict__ out)
{
    __shared__ float s_t[256][16];              // per-thread t0|t1 (16 KB)

    const int b  = blockIdx.x >> 3;             // / NCG
    const int cg = blockIdx.x & (NCG - 1);
    const int cp = threadIdx.x & (CPB - 1);     // channel-pair within group
    const int q  = threadIdx.x >> 4;            // S-segment index

    const float2* __restrict__ p =
        x2 + ((size_t)b * S_DIM + (size_t)q * SEG) * (C_DIM / 2) + cg * CPB + cp;

    float t0[8], t1[8];
    #pragma unroll
    for (int i = 0; i < 8; ++i) { t0[i] = -CUDART_INF_F; t1[i] = -CUDART_INF_F; }

    #pragma unroll 1
    for (int s = 0; s < SEG; s += 16) {
        float2 buf[16];
        #pragma unroll
        for (int u = 0; u < 16; ++u)
            buf[u] = __ldcs(p + (size_t)(s + u) * (C_DIM / 2));

        float f[8], g[8];
        // channel .x
        #pragma unroll
        for (int u = 0; u < 8; ++u) { f[u] = buf[u].x; g[u] = buf[u + 8].x; }
        sort8_desc(f); sort8_desc(g);
        merge8_desc(f, g);      // f = sorted top-8 of the 16
        merge8_desc(t0, f);
        // channel .y
        #pragma unroll
        for (int u = 0; u < 8; ++u) { f[u] = buf[u].y; g[u] = buf[u + 8].y; }
        sort8_desc(f); sort8_desc(g);
        merge8_desc(f, g);
        merge8_desc(t1, f);
    }

    // Publish this thread's two sorted top-8s.
    #pragma unroll
    for (int i = 0; i < 8; ++i) {
        s_t[threadIdx.x][i]     = t0[i];
        s_t[threadIdx.x][8 + i] = t1[i];
    }
    __syncthreads();

    // One warp merges: thread r handles channel (rcp*2 + half); merges the
    // 16 q-segment records and writes the final sorted top-8.
    if (threadIdx.x < 32) {
        const int rcp  = threadIdx.x >> 1;      // 0..15
        const int half = threadIdx.x & 1;       // 0 = .x, 1 = .y
        const int off  = half * 8;

        float m[8];
        #pragma unroll
        for (int i = 0; i < 8; ++i) m[i] = s_t[rcp][off + i];       // q = 0
        #pragma unroll
        for (int j = 1; j < QDIV; ++j) {
            float g[8];
            #pragma unroll
            for (int i = 0; i < 8; ++i) g[i] = s_t[j * CPB + rcp][off + i];
            merge8_desc(m, g);
        }

        const int ch = cg * (CPB * 2) + rcp * 2 + half;
        float* __restrict__ o = out + (size_t)b * K_TOP * C_DIM + ch;
        #pragma unroll
        for (int k = 0; k < K_TOP; ++k)
            o[(size_t)k * C_DIM] = m[k];
    }
}

extern "C" void kernel_launch(void* const* d_in, const int* in_sizes, int n_in,
                              void* d_out, int out_size) {
    const float2* x2 = (const float2*)d_in[0];
    float* out = (float*)d_out;
    kmax_onepass_kernel<<<GRID1, 256>>>(x2, out);
}